// round 7
// baseline (speedup 1.0000x reference)
#include <cuda_runtime.h>
#include <cuda_bf16.h>

// FasterPConv: B=2, N=80000, K=16 neighbors, C=32 channels, H=4 heads, M=8 mid.
// out[b,n,m,c] = sum_k feat[b, idx[b,n,k], c] * guid[b,n,k, c/(C/H)] * w[b,n,k,m]
//
// One warp per point n, lane = channel c.
// R5 changes (L1TEX was 88.6% = bottleneck; scalar broadcast LDS dominated):
//   - sw read as 2 uniform LDS.128 per k (ulonglong2 -> pre-packed f32x2 pairs)
//     instead of 8 scalar broadcast LDS   (128 -> 32 wavefronts/point)
//   - sidx read as 4 uniform int4 LDS     (16 -> 4 wavefronts/point)
//   - accumulators packed in f32x2; inner loop uses fma.rn.f32x2 (FFMA2),
//     halving fma-pipe issue slots, identical rounding to fmaf

constexpr int C = 32;
constexpr int K = 16;
constexpr int H = 4;
constexpr int M = 8;
constexpr int WARPS_PER_BLOCK = 8;
constexpr int THREADS = WARPS_PER_BLOCK * 32;

__device__ __forceinline__ void ffma2(unsigned long long& d,
                                      unsigned long long a,
                                      unsigned long long b) {
    asm("fma.rn.f32x2 %0, %1, %2, %0;" : "+l"(d) : "l"(a), "l"(b));
}

__global__ __launch_bounds__(THREADS)
void fasterpconv_kernel(const float* __restrict__ feat,
                        const int* __restrict__ inds,
                        const float* __restrict__ guid,
                        const float* __restrict__ wn,
                        float* __restrict__ out,
                        int BN, int N) {
    __shared__ __align__(16) float sw[WARPS_PER_BLOCK][K * M];   // 128 f32 per warp
    __shared__ __align__(16) float sg[WARPS_PER_BLOCK][K * H];   // 64 f32 per warp
    __shared__ __align__(16) int   sidx[WARPS_PER_BLOCK][K];     // 16 i32 per warp

    const int w    = threadIdx.x >> 5;
    const int lane = threadIdx.x & 31;
    const int p    = blockIdx.x * WARPS_PER_BLOCK + w;   // point index in [0, B*N)
    if (p >= BN) return;

    // ---- stage per-point small tensors into shared (vectorized) ----
    {
        const float4* wsrc = reinterpret_cast<const float4*>(wn + (size_t)p * (K * M));
        reinterpret_cast<float4*>(sw[w])[lane] = wsrc[lane];      // 128 f32
        if (lane < 16) {
            const float4* gsrc = reinterpret_cast<const float4*>(guid + (size_t)p * (K * H));
            reinterpret_cast<float4*>(sg[w])[lane] = gsrc[lane];  // 64 f32
            sidx[w][lane] = inds[(size_t)p * K + lane];           // 16 i32
        }
    }
    __syncwarp();

    // b = p / N with B=2: branch-free compare instead of integer division.
    const size_t batch_off = (p >= N) ? (size_t)N * C : 0;
    const float* fbase = feat + batch_off + lane;

    // Indices via 4 uniform int4 broadcasts (4 wavefronts instead of 16).
    int idxr[K];
    {
        const int4* ip = reinterpret_cast<const int4*>(sidx[w]);
#pragma unroll
        for (int j = 0; j < 4; j++) {
            const int4 v = ip[j];
            idxr[j * 4 + 0] = v.x;
            idxr[j * 4 + 1] = v.y;
            idxr[j * 4 + 2] = v.z;
            idxr[j * 4 + 3] = v.w;
        }
    }

    // Front-batch the 16 gathers for max MLP.
    float fv[K];
#pragma unroll
    for (int k = 0; k < K; k++) {
        fv[k] = __ldg(fbase + (size_t)idxr[k] * C);
    }

    const int head = lane >> 3;   // c / (C/H) with C/H = 8

    // Packed f32x2 accumulators: accp[j] = (acc[2j], acc[2j+1])
    unsigned long long accp[M / 2] = {0ull, 0ull, 0ull, 0ull};

#pragma unroll
    for (int k = 0; k < K; k++) {
        const float v = fv[k] * sg[w][k * H + head];
        unsigned long long vv;
        asm("mov.b64 %0, {%1, %1};" : "=l"(vv) : "f"(v));
        // Two uniform LDS.128: weight pairs arrive pre-packed as f32x2.
        const ulonglong2* swp = reinterpret_cast<const ulonglong2*>(&sw[w][k * M]);
        const ulonglong2 w01 = swp[0];   // (w0,w1),(w2,w3)
        const ulonglong2 w23 = swp[1];   // (w4,w5),(w6,w7)
        ffma2(accp[0], vv, w01.x);
        ffma2(accp[1], vv, w01.y);
        ffma2(accp[2], vv, w23.x);
        ffma2(accp[3], vv, w23.y);
    }

    // ---- write out[p, m, c] : 8 coalesced 128B stores per warp ----
    float* op = out + (size_t)p * (M * C) + lane;
#pragma unroll
    for (int j = 0; j < M / 2; j++) {
        float lo, hi;
        asm("mov.b64 {%0, %1}, %2;" : "=f"(lo), "=f"(hi) : "l"(accp[j]));
        op[(2 * j + 0) * C] = lo;
        op[(2 * j + 1) * C] = hi;
    }
}

extern "C" void kernel_launch(void* const* d_in, const int* in_sizes, int n_in,
                              void* d_out, int out_size) {
    const float* feat = (const float*)d_in[0];   // [B,N,C]
    const int*   inds = (const int*)d_in[1];     // [B,N,K]
    const float* guid = (const float*)d_in[2];   // [B,N,K,H]
    const float* wn   = (const float*)d_in[3];   // [B,N,K,M]
    float* out = (float*)d_out;                  // [B,N,M*C]

    const int BN = in_sizes[1] / K;              // B*N points total
    const int N  = (in_sizes[0] / C) / 2;        // per-batch N (B=2)

    const int blocks = (BN + WARPS_PER_BLOCK - 1) / WARPS_PER_BLOCK;
    fasterpconv_kernel<<<blocks, THREADS>>>(feat, inds, guid, wn, out, BN, N);
}